// round 9
// baseline (speedup 1.0000x reference)
#include <cuda_runtime.h>

// RK4 over f(y) = tanh(y@W1+b1)@W2 + b2.  S*B=3072 rows, D=32, H=128, T=256.
//
// R8: hidden-split cooperative pairs.
// Block = 64 threads = 2 warps = ONE row-group of 4 rows.
//   warp w owns hidden units j = g + 8i for i in [8w, 8w+8)   (64 units)
//   lane = (g = lane&7, s = lane>>3); lane owns state quarter [8s..8s+7]
// Each warp computes a partial k over its 64 hidden units (quarter-slot
// scheme from R7: per-quarter packed-FMA dot, 2-round shfl butterfly over s,
// tanh, scatter, 3-round butterfly over g), then the two warps exchange
// partials through a padded smem slot (+1 __syncthreads, ping-pong buffered)
// and both finish k = p_self + p_other + b2.
// vs R7: warps/SM doubles (5.2 -> 10.4, 2.6/SMSP) with IDENTICAL total
// weight-crossbar traffic -> latency chains finally have overlap cover.

#define DIM   32
#define HID   128
#define NT    256
#define NROWS 3072
#define TPB   64
#define RPB   4                    // rows per block (one row-group)
#define NBLK  (NROWS/RPB)          // 768

typedef unsigned long long ull;

__device__ __forceinline__ ull fma2(ull a, ull b, ull c) {
    ull d;
    asm("fma.rn.f32x2 %0, %1, %2, %3;" : "=l"(d) : "l"(a), "l"(b), "l"(c));
    return d;
}
__device__ __forceinline__ ull add2(ull a, ull b) {
    ull d;
    asm("add.rn.f32x2 %0, %1, %2;" : "=l"(d) : "l"(a), "l"(b));
    return d;
}
__device__ __forceinline__ ull pack2(float lo, float hi) {
    ull d;
    asm("mov.b64 %0, {%1, %2};" : "=l"(d) : "f"(lo), "f"(hi));
    return d;
}
__device__ __forceinline__ void unpack2(ull v, float& lo, float& hi) {
    asm("mov.b64 {%0, %1}, %2;" : "=f"(lo), "=f"(hi) : "l"(v));
}

// accurate fast tanh: 1 - 2/(exp(2x)+1); ~1e-7 abs err, saturates at +/-inf.
__device__ __forceinline__ float tanh_fast(float x) {
    float e = __expf(2.0f * x);
    return 1.0f - __fdividef(2.0f, e + 1.0f);
}

// One f evaluation for the block's 4 rows (this warp's 64-hidden half,
// then cross-warp combine). in/kq: [row][quarter-f32x2].
// Weight pointers are pre-offset to this warp's i-plane range.
// xk: [buf][warp][s][9] ulonglong2 (8 used + 1 pad -> 144B s-stride,
// conflict-free 4-lane writes).
__device__ __forceinline__ void feval(
    const ull in[RPB][4], ull kq[RPB][4],
    const ulonglong2* __restrict__ w1aL, const ulonglong2* __restrict__ w1bL,
    const ulonglong2* __restrict__ w2aL, const ulonglong2* __restrict__ w2bL,
    const float* __restrict__ b1L, const ull b2q[4],
    ulonglong2 (* __restrict__ xk)[2][4][9],
    int warp, int s, int g, int buf)
{
    ull p[RPB][4];
#pragma unroll
    for (int r = 0; r < RPB; ++r)
#pragma unroll
        for (int d = 0; d < 4; ++d) p[r][d] = 0ull;

#pragma unroll
    for (int i = 0; i < 8; ++i) {
        const ulonglong2 wa = w1aL[i * 32];   // W1[8s+0..3 , j]
        const ulonglong2 wb = w1bL[i * 32];   // W1[8s+4..7 , j]
        const float b1j = b1L[8 * i];

        // per-quarter dots for the 4 rows
        float hs[RPB];
#pragma unroll
        for (int r = 0; r < RPB; ++r) {
            ull t0 = fma2(in[r][0], wa.x, 0ull);
            ull t1 = fma2(in[r][2], wb.x, 0ull);
            t0 = fma2(in[r][1], wa.y, t0);
            t1 = fma2(in[r][3], wb.y, t1);
            float lo, hi;
            unpack2(add2(t0, t1), lo, hi);
            hs[r] = lo + hi;
        }

        // butterfly over s (lanes ^8, ^16); 2 rows per packed value
        ull q01 = pack2(hs[0], hs[1]);
        ull q23 = pack2(hs[2], hs[3]);
        q01 = add2(q01, __shfl_xor_sync(0xffffffffu, q01, 8));
        q23 = add2(q23, __shfl_xor_sync(0xffffffffu, q23, 8));
        q01 = add2(q01, __shfl_xor_sync(0xffffffffu, q01, 16));
        q23 = add2(q23, __shfl_xor_sync(0xffffffffu, q23, 16));
        float f0, f1, f2, f3;
        unpack2(q01, f0, f1);
        unpack2(q23, f2, f3);

        const ulonglong2 va = w2aL[i * 32];   // W2[j][8s+0..3]
        const ulonglong2 vb = w2bL[i * 32];   // W2[j][8s+4..7]

        float hr[RPB];
        hr[0] = tanh_fast(f0 + b1j);
        hr[1] = tanh_fast(f1 + b1j);
        hr[2] = tanh_fast(f2 + b1j);
        hr[3] = tanh_fast(f3 + b1j);
#pragma unroll
        for (int r = 0; r < RPB; ++r) {
            const ull hh = pack2(hr[r], hr[r]);
            p[r][0] = fma2(hh, va.x, p[r][0]);
            p[r][1] = fma2(hh, va.y, p[r][1]);
            p[r][2] = fma2(hh, vb.x, p[r][2]);
            p[r][3] = fma2(hh, vb.y, p[r][3]);
        }
    }

    // reduce partial over the 8 g-lanes (lanes ^1, ^2, ^4)
#pragma unroll
    for (int m = 1; m < 8; m <<= 1) {
#pragma unroll
        for (int r = 0; r < RPB; ++r)
#pragma unroll
            for (int d = 0; d < 4; ++d)
                p[r][d] = add2(p[r][d],
                               __shfl_xor_sync(0xffffffffu, p[r][d], m));
    }

    // cross-warp exchange: g==0 lanes (one per s) publish this warp's partial
    if (g == 0) {
        ulonglong2* dst = &xk[buf][warp][s][0];
#pragma unroll
        for (int r = 0; r < RPB; ++r) {
            ulonglong2 v0, v1;
            v0.x = p[r][0]; v0.y = p[r][1];
            v1.x = p[r][2]; v1.y = p[r][3];
            dst[2 * r]     = v0;
            dst[2 * r + 1] = v1;
        }
    }
    __syncthreads();
    {
        const ulonglong2* src = &xk[buf][warp ^ 1][s][0];  // g-broadcast read
#pragma unroll
        for (int r = 0; r < RPB; ++r) {
            ulonglong2 v0 = src[2 * r];
            ulonglong2 v1 = src[2 * r + 1];
            kq[r][0] = add2(add2(p[r][0], v0.x), b2q[0]);
            kq[r][1] = add2(add2(p[r][1], v0.y), b2q[1]);
            kq[r][2] = add2(add2(p[r][2], v1.x), b2q[2]);
            kq[r][3] = add2(add2(p[r][3], v1.y), b2q[3]);
        }
    }
}

__global__ __launch_bounds__(TPB, 6)
void rk4_mlp_kernel(
    const float* __restrict__ first_point,   // [3072, 32]
    const float* __restrict__ time_steps,    // [256]
    const float* __restrict__ W1,            // [32, 128]
    const float* __restrict__ b1,            // [128]
    const float* __restrict__ W2,            // [128, 32]
    const float* __restrict__ b2,            // [32]
    float* __restrict__ out)                 // [3072, 256, 32]
{
    // weight packs: [i-plane][lane]; every warp LDS.128 is 512B all-unique
    __shared__ ulonglong2 w1qA[16][32];  // float4 = W1[8s+0..3 , g+8i]
    __shared__ ulonglong2 w1qB[16][32];  // float4 = W1[8s+4..7 , g+8i]
    __shared__ ulonglong2 w2qA[16][32];  // float4 = W2[g+8i][8s+0..3]
    __shared__ ulonglong2 w2qB[16][32];  // float4 = W2[g+8i][8s+4..7]
    __shared__ float b1s[HID];
    __shared__ float tss[NT];
    __shared__ ulonglong2 xk[2][2][4][9];  // [buf][warp][s][8+pad]

    const int tid = threadIdx.x;

    // ---- stage weights (one-time; scalar writes) ----
    {
        float* a1 = (float*)w1qA; float* a2 = (float*)w1qB;
        float* a3 = (float*)w2qA; float* a4 = (float*)w2qB;
        for (int idx = tid; idx < 16 * 32 * 4; idx += TPB) {
            const int i  = idx >> 7;          // plane
            const int ln = (idx >> 2) & 31;   // lane
            const int f  = idx & 3;           // float within float4
            const int ss = ln >> 3, gg = ln & 7;
            const int j  = gg + 8 * i;
            a1[idx] = W1[(8 * ss + f)     * HID + j];
            a2[idx] = W1[(8 * ss + 4 + f) * HID + j];
            a3[idx] = W2[j * DIM + 8 * ss + f];
            a4[idx] = W2[j * DIM + 8 * ss + 4 + f];
        }
        for (int idx = tid; idx < HID; idx += TPB) b1s[idx] = b1[idx];
        for (int idx = tid; idx < NT;  idx += TPB) tss[idx] = time_steps[idx];
    }
    __syncthreads();

    const int lane = tid & 31;
    const int warp = tid >> 5;
    const int g = lane & 7;
    const int s = lane >> 3;
    const int rbase = blockIdx.x * RPB;

    // this warp's half of the i-planes
    const ulonglong2* w1aL = &w1qA[8 * warp][lane];
    const ulonglong2* w1bL = &w1qB[8 * warp][lane];
    const ulonglong2* w2aL = &w2qA[8 * warp][lane];
    const ulonglong2* w2bL = &w2qB[8 * warp][lane];
    const float* b1L = b1s + 64 * warp + g;

    // b2 quarter, packed (registers)
    ull b2q[4];
#pragma unroll
    for (int d = 0; d < 4; ++d)
        b2q[d] = pack2(b2[8 * s + 2 * d], b2[8 * s + 2 * d + 1]);

    // ---- load initial state: lane's quarter for each of 4 rows ----
    ull y2[RPB][4], acc2[RPB][4], yin2[RPB][4], k2[RPB][4];
#pragma unroll
    for (int r = 0; r < RPB; ++r) {
        const ulonglong2* fp = reinterpret_cast<const ulonglong2*>(
            first_point + (size_t)(rbase + r) * DIM + 8 * s);
        ulonglong2 v0 = fp[0], v1 = fp[1];
        y2[r][0] = v0.x; y2[r][1] = v0.y;
        y2[r][2] = v1.x; y2[r][3] = v1.y;
    }

    // t = 0: warp 0, lanes g<4 write row g's quarter (coalesced)
    if (warp == 0 && g < 4) {
        float* dst = out + (size_t)(rbase + g) * (NT * DIM) + 8 * s;
        ulonglong2 v0, v1;
        v0.x = y2[g][0]; v0.y = y2[g][1];
        v1.x = y2[g][2]; v1.y = y2[g][3];
        reinterpret_cast<ulonglong2*>(dst)[0] = v0;
        reinterpret_cast<ulonglong2*>(dst)[1] = v1;
    }

    // ---- RK4 time loop (sequential) ----
#pragma unroll 1
    for (int t = 0; t < NT - 1; ++t) {
        const float dt  = tss[t + 1] - tss[t];
        const ull dt6p = pack2(dt * (1.0f / 6.0f), dt * (1.0f / 6.0f));
        const ull dt3p = pack2(dt * (1.0f / 3.0f), dt * (1.0f / 3.0f));
        const ull dthp = pack2(0.5f * dt, 0.5f * dt);
        const ull dtfp = pack2(dt, dt);

        // k1  (buf 0)
        feval(y2, k2, w1aL, w1bL, w2aL, w2bL, b1L, b2q, xk, warp, s, g, 0);
#pragma unroll
        for (int r = 0; r < RPB; ++r)
#pragma unroll
            for (int d = 0; d < 4; ++d) {
                acc2[r][d] = fma2(dt6p, k2[r][d], y2[r][d]);
                yin2[r][d] = fma2(dthp, k2[r][d], y2[r][d]);
            }
        // k2  (buf 1)
        feval(yin2, k2, w1aL, w1bL, w2aL, w2bL, b1L, b2q, xk, warp, s, g, 1);
#pragma unroll
        for (int r = 0; r < RPB; ++r)
#pragma unroll
            for (int d = 0; d < 4; ++d) {
                acc2[r][d] = fma2(dt3p, k2[r][d], acc2[r][d]);
                yin2[r][d] = fma2(dthp, k2[r][d], y2[r][d]);
            }
        // k3  (buf 0)
        feval(yin2, k2, w1aL, w1bL, w2aL, w2bL, b1L, b2q, xk, warp, s, g, 0);
#pragma unroll
        for (int r = 0; r < RPB; ++r)
#pragma unroll
            for (int d = 0; d < 4; ++d) {
                acc2[r][d] = fma2(dt3p, k2[r][d], acc2[r][d]);
                yin2[r][d] = fma2(dtfp, k2[r][d], y2[r][d]);
            }
        // k4  (buf 1)
        feval(yin2, k2, w1aL, w1bL, w2aL, w2bL, b1L, b2q, xk, warp, s, g, 1);
#pragma unroll
        for (int r = 0; r < RPB; ++r)
#pragma unroll
            for (int d = 0; d < 4; ++d)
                y2[r][d] = fma2(dt6p, k2[r][d], acc2[r][d]);

        // store y_{t+1}: warp 0, lanes g<4
        if (warp == 0 && g < 4) {
            float* dst = out + (size_t)(rbase + g) * (NT * DIM)
                       + (size_t)(t + 1) * DIM + 8 * s;
            ulonglong2 v0, v1;
            v0.x = y2[g][0]; v0.y = y2[g][1];
            v1.x = y2[g][2]; v1.y = y2[g][3];
            reinterpret_cast<ulonglong2*>(dst)[0] = v0;
            reinterpret_cast<ulonglong2*>(dst)[1] = v1;
        }
    }
}

extern "C" void kernel_launch(void* const* d_in, const int* in_sizes, int n_in,
                              void* d_out, int out_size) {
    const float* first_point = (const float*)d_in[0];  // [3,1024,32]
    const float* time_steps  = (const float*)d_in[1];  // [256]
    const float* W1          = (const float*)d_in[2];  // [32,128]
    const float* b1          = (const float*)d_in[3];  // [128]
    const float* W2          = (const float*)d_in[4];  // [128,32]
    const float* b2          = (const float*)d_in[5];  // [32]
    float* out = (float*)d_out;                        // [3,1024,256,32]

    rk4_mlp_kernel<<<NBLK, TPB>>>(first_point, time_steps, W1, b1, W2, b2, out);
}

// round 10
// speedup vs baseline: 1.1573x; 1.1573x over previous
#include <cuda_runtime.h>

// RK4 over f(y) = tanh(y@W1+b1)@W2 + b2.  S*B=3072 rows, D=32, H=128, T=256.
//
// R10 = R7 (best: 3267us, autonomous warps) + tanh slot-dedup.
// Quarter-slot layout: lane = (g = lane&7, s = lane>>3).
//   - lane owns hidden units j = g + 8i  (i = 0..15)
//   - lane owns state-quarter dims [8s .. 8s+7]  (4 packed f32x2 regs / row)
// One warp carries 4 rows; weights loaded once per feval, reused across rows.
// NEW vs R7: after the s-butterfly all-reduce of the dot products, slot s
// evaluates ONLY row s's tanh (was: all 4 slots redundantly evaluated all 4
// rows -> 4x MUFU + fma waste). The four h values are then re-broadcast to
// all slots with two shfls (+SELs on the idle ALU pipe). Bitwise-identical
// math -> rel_err unchanged.

#define DIM   32
#define HID   128
#define NT    256
#define NROWS 3072
#define TPB   64
#define RPW   4                    // rows per warp
#define RPB   ((TPB/32)*RPW)       // 8 rows per block
#define NBLK  (NROWS/RPB)          // 384

typedef unsigned long long ull;

__device__ __forceinline__ ull fma2(ull a, ull b, ull c) {
    ull d;
    asm("fma.rn.f32x2 %0, %1, %2, %3;" : "=l"(d) : "l"(a), "l"(b), "l"(c));
    return d;
}
__device__ __forceinline__ ull add2(ull a, ull b) {
    ull d;
    asm("add.rn.f32x2 %0, %1, %2;" : "=l"(d) : "l"(a), "l"(b));
    return d;
}
__device__ __forceinline__ ull pack2(float lo, float hi) {
    ull d;
    asm("mov.b64 %0, {%1, %2};" : "=l"(d) : "f"(lo), "f"(hi));
    return d;
}
__device__ __forceinline__ void unpack2(ull v, float& lo, float& hi) {
    asm("mov.b64 {%0, %1}, %2;" : "=f"(lo), "=f"(hi) : "l"(v));
}

// accurate fast tanh: 1 - 2/(exp(2x)+1); ~1e-7 abs err, saturates at +/-inf.
__device__ __forceinline__ float tanh_fast(float x) {
    float e = __expf(2.0f * x);
    return 1.0f - __fdividef(2.0f, e + 1.0f);
}

// One f evaluation for the warp's 4 rows.
// in/kq: [row][quarter-f32x2]; weights via per-lane pointers (stride 32
// ulonglong2 = one [i] plane).
__device__ __forceinline__ void feval(
    const ull in[RPW][4], ull kq[RPW][4],
    const ulonglong2* __restrict__ w1aL, const ulonglong2* __restrict__ w1bL,
    const ulonglong2* __restrict__ w2aL, const ulonglong2* __restrict__ w2bL,
    const float* __restrict__ b1s, const ull b2q[4], int g, int s)
{
    const bool sLo = (s & 1) != 0;   // position within s-pair
    const bool sHi = (s & 2) != 0;   // which s-pair

#pragma unroll
    for (int r = 0; r < RPW; ++r)
#pragma unroll
        for (int d = 0; d < 4; ++d) kq[r][d] = 0ull;

#pragma unroll 4
    for (int i = 0; i < 16; ++i) {
        const ulonglong2 wa = w1aL[i * 32];   // W1[8s+0..3 , g+8i]
        const ulonglong2 wb = w1bL[i * 32];   // W1[8s+4..7 , g+8i]
        const float b1j = b1s[g + 8 * i];

        // per-quarter dots for the 4 rows
        float hs[RPW];
#pragma unroll
        for (int r = 0; r < RPW; ++r) {
            ull t0 = fma2(in[r][0], wa.x, 0ull);
            ull t1 = fma2(in[r][2], wb.x, 0ull);
            t0 = fma2(in[r][1], wa.y, t0);
            t1 = fma2(in[r][3], wb.y, t1);
            float lo, hi;
            unpack2(add2(t0, t1), lo, hi);
            hs[r] = lo + hi;
        }

        // butterfly over s (lanes ^8, ^16); 2 rows per packed value
        ull q01 = pack2(hs[0], hs[1]);
        ull q23 = pack2(hs[2], hs[3]);
        q01 = add2(q01, __shfl_xor_sync(0xffffffffu, q01, 8));
        q23 = add2(q23, __shfl_xor_sync(0xffffffffu, q23, 8));
        q01 = add2(q01, __shfl_xor_sync(0xffffffffu, q01, 16));
        q23 = add2(q23, __shfl_xor_sync(0xffffffffu, q23, 16));
        float f0, f1, f2, f3;
        unpack2(q01, f0, f1);
        unpack2(q23, f2, f3);

        // slot s evaluates ONLY row s's tanh (dedup: was 4x redundant)
        const float fA = sLo ? f1 : f0;      // row (s) within pair from q01
        const float fB = sLo ? f3 : f2;      // row (s) within pair from q23
        const float fs = sHi ? fB : fA;
        const float h  = tanh_fast(fs + b1j);

        // re-broadcast the 4 h's to every slot: ^8 (scalar) then ^16 (packed)
        const float ho = __shfl_xor_sync(0xffffffffu, h, 8);  // from s^1
        const float hl = sLo ? ho : h;       // h of even slot in this pair
        const float hu = sLo ? h : ho;       // h of odd slot in this pair
        const ull hp = pack2(hl, hu);        // (h_{2a}, h_{2a+1}), a = s>>1
        const ull hq = __shfl_xor_sync(0xffffffffu, hp, 16);  // other pair
        const ull h01 = sHi ? hq : hp;       // (h0, h1)
        const ull h23 = sHi ? hp : hq;       // (h2, h3)
        float h0, h1, h2, h3;
        unpack2(h01, h0, h1);
        unpack2(h23, h2, h3);

        const ulonglong2 va = w2aL[i * 32];   // W2[g+8i][8s+0..3]
        const ulonglong2 vb = w2bL[i * 32];   // W2[g+8i][8s+4..7]

        ull hhr[RPW];
        hhr[0] = pack2(h0, h0);
        hhr[1] = pack2(h1, h1);
        hhr[2] = pack2(h2, h2);
        hhr[3] = pack2(h3, h3);
#pragma unroll
        for (int r = 0; r < RPW; ++r) {
            kq[r][0] = fma2(hhr[r], va.x, kq[r][0]);
            kq[r][1] = fma2(hhr[r], va.y, kq[r][1]);
            kq[r][2] = fma2(hhr[r], vb.x, kq[r][2]);
            kq[r][3] = fma2(hhr[r], vb.y, kq[r][3]);
        }
    }

    // reduce partial k over the 8 g-lanes (lanes ^1, ^2, ^4), then + b2
#pragma unroll
    for (int m = 1; m < 8; m <<= 1) {
#pragma unroll
        for (int r = 0; r < RPW; ++r)
#pragma unroll
            for (int d = 0; d < 4; ++d)
                kq[r][d] = add2(kq[r][d],
                                __shfl_xor_sync(0xffffffffu, kq[r][d], m));
    }
#pragma unroll
    for (int r = 0; r < RPW; ++r)
#pragma unroll
        for (int d = 0; d < 4; ++d) kq[r][d] = add2(kq[r][d], b2q[d]);
}

__global__ __launch_bounds__(TPB)
void rk4_mlp_kernel(
    const float* __restrict__ first_point,   // [3072, 32]
    const float* __restrict__ time_steps,    // [256]
    const float* __restrict__ W1,            // [32, 128]
    const float* __restrict__ b1,            // [128]
    const float* __restrict__ W2,            // [128, 32]
    const float* __restrict__ b2,            // [32]
    float* __restrict__ out)                 // [3072, 256, 32]
{
    // weight packs: [i][lane]; every warp LDS.128 is 512B all-unique
    __shared__ ulonglong2 w1qA[16][32];  // float4 = W1[8s+0..3 , g+8i]
    __shared__ ulonglong2 w1qB[16][32];  // float4 = W1[8s+4..7 , g+8i]
    __shared__ ulonglong2 w2qA[16][32];  // float4 = W2[g+8i][8s+0..3]
    __shared__ ulonglong2 w2qB[16][32];  // float4 = W2[g+8i][8s+4..7]
    __shared__ float b1s[HID];
    __shared__ float tss[NT];

    const int tid = threadIdx.x;

    // ---- stage weights (one-time; scalar writes) ----
    {
        float* a1 = (float*)w1qA; float* a2 = (float*)w1qB;
        float* a3 = (float*)w2qA; float* a4 = (float*)w2qB;
        for (int idx = tid; idx < 16 * 32 * 4; idx += TPB) {
            const int i  = idx >> 7;          // plane
            const int ln = (idx >> 2) & 31;   // lane
            const int f  = idx & 3;           // float within float4
            const int ss = ln >> 3, gg = ln & 7;
            const int j  = gg + 8 * i;
            a1[idx] = W1[(8 * ss + f)     * HID + j];
            a2[idx] = W1[(8 * ss + 4 + f) * HID + j];
            a3[idx] = W2[j * DIM + 8 * ss + f];
            a4[idx] = W2[j * DIM + 8 * ss + 4 + f];
        }
        for (int idx = tid; idx < HID; idx += TPB) b1s[idx] = b1[idx];
        for (int idx = tid; idx < NT;  idx += TPB) tss[idx] = time_steps[idx];
    }
    __syncthreads();

    const int lane = tid & 31;
    const int warp = tid >> 5;
    const int g = lane & 7;
    const int s = lane >> 3;
    const int rbase = blockIdx.x * RPB + warp * RPW;

    const ulonglong2* w1aL = &w1qA[0][lane];
    const ulonglong2* w1bL = &w1qB[0][lane];
    const ulonglong2* w2aL = &w2qA[0][lane];
    const ulonglong2* w2bL = &w2qB[0][lane];

    // b2 quarter, packed (registers)
    ull b2q[4];
#pragma unroll
    for (int d = 0; d < 4; ++d)
        b2q[d] = pack2(b2[8 * s + 2 * d], b2[8 * s + 2 * d + 1]);

    // ---- load initial state: lane's quarter for each of 4 rows ----
    ull y2[RPW][4], acc2[RPW][4], yin2[RPW][4], k2[RPW][4];
#pragma unroll
    for (int r = 0; r < RPW; ++r) {
        const ulonglong2* fp = reinterpret_cast<const ulonglong2*>(
            first_point + (size_t)(rbase + r) * DIM + 8 * s);
        ulonglong2 v0 = fp[0], v1 = fp[1];
        y2[r][0] = v0.x; y2[r][1] = v0.y;
        y2[r][2] = v1.x; y2[r][3] = v1.y;
    }

    // t = 0: lanes g<4 write row g's quarter (coalesced 128B per row)
    if (g < 4) {
        float* dst = out + (size_t)(rbase + g) * (NT * DIM) + 8 * s;
        ulonglong2 v0, v1;
        v0.x = y2[g][0]; v0.y = y2[g][1];
        v1.x = y2[g][2]; v1.y = y2[g][3];
        reinterpret_cast<ulonglong2*>(dst)[0] = v0;
        reinterpret_cast<ulonglong2*>(dst)[1] = v1;
    }

    // ---- RK4 time loop (sequential) ----
#pragma unroll 1
    for (int t = 0; t < NT - 1; ++t) {
        const float dt  = tss[t + 1] - tss[t];
        const ull dt6p = pack2(dt * (1.0f / 6.0f), dt * (1.0f / 6.0f));
        const ull dt3p = pack2(dt * (1.0f / 3.0f), dt * (1.0f / 3.0f));
        const ull dthp = pack2(0.5f * dt, 0.5f * dt);
        const ull dtfp = pack2(dt, dt);

        // k1
        feval(y2, k2, w1aL, w1bL, w2aL, w2bL, b1s, b2q, g, s);
#pragma unroll
        for (int r = 0; r < RPW; ++r)
#pragma unroll
            for (int d = 0; d < 4; ++d) {
                acc2[r][d] = fma2(dt6p, k2[r][d], y2[r][d]);
                yin2[r][d] = fma2(dthp, k2[r][d], y2[r][d]);
            }
        // k2
        feval(yin2, k2, w1aL, w1bL, w2aL, w2bL, b1s, b2q, g, s);
#pragma unroll
        for (int r = 0; r < RPW; ++r)
#pragma unroll
            for (int d = 0; d < 4; ++d) {
                acc2[r][d] = fma2(dt3p, k2[r][d], acc2[r][d]);
                yin2[r][d] = fma2(dthp, k2[r][d], y2[r][d]);
            }
        // k3
        feval(yin2, k2, w1aL, w1bL, w2aL, w2bL, b1s, b2q, g, s);
#pragma unroll
        for (int r = 0; r < RPW; ++r)
#pragma unroll
            for (int d = 0; d < 4; ++d) {
                acc2[r][d] = fma2(dt3p, k2[r][d], acc2[r][d]);
                yin2[r][d] = fma2(dtfp, k2[r][d], y2[r][d]);
            }
        // k4
        feval(yin2, k2, w1aL, w1bL, w2aL, w2bL, b1s, b2q, g, s);
#pragma unroll
        for (int r = 0; r < RPW; ++r)
#pragma unroll
            for (int d = 0; d < 4; ++d)
                y2[r][d] = fma2(dt6p, k2[r][d], acc2[r][d]);

        // store y_{t+1}
        if (g < 4) {
            float* dst = out + (size_t)(rbase + g) * (NT * DIM)
                       + (size_t)(t + 1) * DIM + 8 * s;
            ulonglong2 v0, v1;
            v0.x = y2[g][0]; v0.y = y2[g][1];
            v1.x = y2[g][2]; v1.y = y2[g][3];
            reinterpret_cast<ulonglong2*>(dst)[0] = v0;
            reinterpret_cast<ulonglong2*>(dst)[1] = v1;
        }
    }
}

extern "C" void kernel_launch(void* const* d_in, const int* in_sizes, int n_in,
                              void* d_out, int out_size) {
    const float* first_point = (const float*)d_in[0];  // [3,1024,32]
    const float* time_steps  = (const float*)d_in[1];  // [256]
    const float* W1          = (const float*)d_in[2];  // [32,128]
    const float* b1          = (const float*)d_in[3];  // [128]
    const float* W2          = (const float*)d_in[4];  // [128,32]
    const float* b2          = (const float*)d_in[5];  // [32]
    float* out = (float*)d_out;                        // [3,1024,256,32]

    rk4_mlp_kernel<<<NBLK, TPB>>>(first_point, time_steps, W1, b1, W2, b2, out);
}

// round 11
// speedup vs baseline: 1.3763x; 1.1893x over previous
#include <cuda_runtime.h>

// RK4 over f(y) = tanh(y@W1+b1)@W2 + b2.  S*B=3072 rows, D=32, H=128, T=256.
//
// R11 = R10 quarter-slot scheme + latency restructure:
//  (a) feval split into pass A (dot+butterfly+tanh, h staged in regs, 8-wide
//      unroll -> 8 independent latency chains in the issue window) and pass B
//      (pure register FMA scatter). R10 interleaved them, serializing chains.
//  (b) RK4 rewritten as a 4-substep loop with branch-selected coefficients so
//      feval is emitted ONCE (body ~10KB vs ~22KB) -> I$-friendly despite the
//      wider unroll.
// Layout unchanged: lane=(g=lane&7, s=lane>>3); lane owns j=g+8i and state
// quarter [8s..8s+7]; warp carries 4 rows; weights in smem [i][lane] packs
// (every LDS.128 moves 512B all-unique); slot-dedup'd exp-based tanh
// (bitwise-identical math to R10, rel_err 7.9e-7).

#define DIM   32
#define HID   128
#define NT    256
#define NROWS 3072
#define TPB   64
#define RPW   4                    // rows per warp
#define RPB   ((TPB/32)*RPW)       // 8 rows per block
#define NBLK  (NROWS/RPB)          // 384

typedef unsigned long long ull;

__device__ __forceinline__ ull fma2(ull a, ull b, ull c) {
    ull d;
    asm("fma.rn.f32x2 %0, %1, %2, %3;" : "=l"(d) : "l"(a), "l"(b), "l"(c));
    return d;
}
__device__ __forceinline__ ull add2(ull a, ull b) {
    ull d;
    asm("add.rn.f32x2 %0, %1, %2;" : "=l"(d) : "l"(a), "l"(b));
    return d;
}
__device__ __forceinline__ ull pack2(float lo, float hi) {
    ull d;
    asm("mov.b64 %0, {%1, %2};" : "=l"(d) : "f"(lo), "f"(hi));
    return d;
}
__device__ __forceinline__ void unpack2(ull v, float& lo, float& hi) {
    asm("mov.b64 {%0, %1}, %2;" : "=f"(lo), "=f"(hi) : "l"(v));
}

// accurate fast tanh: 1 - 2/(exp(2x)+1); ~1e-7 abs err, saturates at +/-inf.
__device__ __forceinline__ float tanh_fast(float x) {
    float e = __expf(2.0f * x);
    return 1.0f - __fdividef(2.0f, e + 1.0f);
}

// One f evaluation for the warp's 4 rows.  in/kq: [row][quarter-f32x2].
// Weight pointers pre-offset per lane (stride 32 ulonglong2 per i-plane).
// b1L pre-offset to b1s+g.
__device__ __forceinline__ void feval(
    const ull in[RPW][4], ull kq[RPW][4],
    const ulonglong2* __restrict__ w1aL, const ulonglong2* __restrict__ w1bL,
    const ulonglong2* __restrict__ w2aL, const ulonglong2* __restrict__ w2bL,
    const float* __restrict__ b1L, const ull b2q[4], int s)
{
    const bool sLo = (s & 1) != 0;   // position within s-pair
    const bool sHi = (s & 2) != 0;   // which s-pair

#pragma unroll
    for (int r = 0; r < RPW; ++r)
#pragma unroll
        for (int d = 0; d < 4; ++d) kq[r][d] = 0ull;

#pragma unroll 1
    for (int half = 0; half < 2; ++half) {
        const ulonglong2* waP = w1aL + half * 8 * 32;
        const ulonglong2* wbP = w1bL + half * 8 * 32;
        const ulonglong2* vaP = w2aL + half * 8 * 32;
        const ulonglong2* vbP = w2bL + half * 8 * 32;
        const float* b1P = b1L + half * 64;

        // ---- pass A: dots + butterflies + tanh; stage h in registers ----
        ull h01s[8], h23s[8];
#pragma unroll
        for (int ii = 0; ii < 8; ++ii) {
            const ulonglong2 wa = waP[ii * 32];   // W1[8s+0..3 , j]
            const ulonglong2 wb = wbP[ii * 32];   // W1[8s+4..7 , j]
            const float b1j = b1P[8 * ii];

            float hs[RPW];
#pragma unroll
            for (int r = 0; r < RPW; ++r) {
                ull t0 = fma2(in[r][0], wa.x, 0ull);
                ull t1 = fma2(in[r][2], wb.x, 0ull);
                t0 = fma2(in[r][1], wa.y, t0);
                t1 = fma2(in[r][3], wb.y, t1);
                float lo, hi;
                unpack2(add2(t0, t1), lo, hi);
                hs[r] = lo + hi;
            }

            // butterfly over s (lanes ^8, ^16); 2 rows per packed value
            ull q01 = pack2(hs[0], hs[1]);
            ull q23 = pack2(hs[2], hs[3]);
            q01 = add2(q01, __shfl_xor_sync(0xffffffffu, q01, 8));
            q23 = add2(q23, __shfl_xor_sync(0xffffffffu, q23, 8));
            q01 = add2(q01, __shfl_xor_sync(0xffffffffu, q01, 16));
            q23 = add2(q23, __shfl_xor_sync(0xffffffffu, q23, 16));
            float f0, f1, f2, f3;
            unpack2(q01, f0, f1);
            unpack2(q23, f2, f3);

            // slot s evaluates ONLY row s's tanh (dedup)
            const float fA = sLo ? f1 : f0;
            const float fB = sLo ? f3 : f2;
            const float fs = sHi ? fB : fA;
            const float h  = tanh_fast(fs + b1j);

            // re-broadcast the 4 h's: ^8 (scalar) then ^16 (packed)
            const float ho = __shfl_xor_sync(0xffffffffu, h, 8);
            const float hl = sLo ? ho : h;
            const float hu = sLo ? h : ho;
            const ull hp = pack2(hl, hu);
            const ull hq = __shfl_xor_sync(0xffffffffu, hp, 16);
            h01s[ii] = sHi ? hq : hp;        // (h0, h1)
            h23s[ii] = sHi ? hp : hq;        // (h2, h3)
        }

        // ---- pass B: pure-register scatter (16 independent FMA chains) ----
#pragma unroll
        for (int ii = 0; ii < 8; ++ii) {
            const ulonglong2 va = vaP[ii * 32];   // W2[j][8s+0..3]
            const ulonglong2 vb = vbP[ii * 32];   // W2[j][8s+4..7]
            float h0, h1, h2, h3;
            unpack2(h01s[ii], h0, h1);
            unpack2(h23s[ii], h2, h3);
            ull hhr[RPW];
            hhr[0] = pack2(h0, h0);
            hhr[1] = pack2(h1, h1);
            hhr[2] = pack2(h2, h2);
            hhr[3] = pack2(h3, h3);
#pragma unroll
            for (int r = 0; r < RPW; ++r) {
                kq[r][0] = fma2(hhr[r], va.x, kq[r][0]);
                kq[r][1] = fma2(hhr[r], va.y, kq[r][1]);
                kq[r][2] = fma2(hhr[r], vb.x, kq[r][2]);
                kq[r][3] = fma2(hhr[r], vb.y, kq[r][3]);
            }
        }
    }

    // reduce partial k over the 8 g-lanes (lanes ^1, ^2, ^4), then + b2
#pragma unroll
    for (int m = 1; m < 8; m <<= 1) {
#pragma unroll
        for (int r = 0; r < RPW; ++r)
#pragma unroll
            for (int d = 0; d < 4; ++d)
                kq[r][d] = add2(kq[r][d],
                                __shfl_xor_sync(0xffffffffu, kq[r][d], m));
    }
#pragma unroll
    for (int r = 0; r < RPW; ++r)
#pragma unroll
        for (int d = 0; d < 4; ++d) kq[r][d] = add2(kq[r][d], b2q[d]);
}

__global__ __launch_bounds__(TPB)
void rk4_mlp_kernel(
    const float* __restrict__ first_point,   // [3072, 32]
    const float* __restrict__ time_steps,    // [256]
    const float* __restrict__ W1,            // [32, 128]
    const float* __restrict__ b1,            // [128]
    const float* __restrict__ W2,            // [128, 32]
    const float* __restrict__ b2,            // [32]
    float* __restrict__ out)                 // [3072, 256, 32]
{
    // weight packs: [i][lane]; every warp LDS.128 is 512B all-unique
    __shared__ ulonglong2 w1qA[16][32];  // float4 = W1[8s+0..3 , g+8i]
    __shared__ ulonglong2 w1qB[16][32];  // float4 = W1[8s+4..7 , g+8i]
    __shared__ ulonglong2 w2qA[16][32];  // float4 = W2[g+8i][8s+0..3]
    __shared__ ulonglong2 w2qB[16][32];  // float4 = W2[g+8i][8s+4..7]
    __shared__ float b1s[HID];
    __shared__ float tss[NT];

    const int tid = threadIdx.x;

    // ---- stage weights (one-time; scalar writes) ----
    {
        float* a1 = (float*)w1qA; float* a2 = (float*)w1qB;
        float* a3 = (float*)w2qA; float* a4 = (float*)w2qB;
        for (int idx = tid; idx < 16 * 32 * 4; idx += TPB) {
            const int i  = idx >> 7;          // plane
            const int ln = (idx >> 2) & 31;   // lane
            const int f  = idx & 3;           // float within float4
            const int ss = ln >> 3, gg = ln & 7;
            const int j  = gg + 8 * i;
            a1[idx] = W1[(8 * ss + f)     * HID + j];
            a2[idx] = W1[(8 * ss + 4 + f) * HID + j];
            a3[idx] = W2[j * DIM + 8 * ss + f];
            a4[idx] = W2[j * DIM + 8 * ss + 4 + f];
        }
        for (int idx = tid; idx < HID; idx += TPB) b1s[idx] = b1[idx];
        for (int idx = tid; idx < NT;  idx += TPB) tss[idx] = time_steps[idx];
    }
    __syncthreads();

    const int lane = tid & 31;
    const int warp = tid >> 5;
    const int g = lane & 7;
    const int s = lane >> 3;
    const int rbase = blockIdx.x * RPB + warp * RPW;

    const ulonglong2* w1aL = &w1qA[0][lane];
    const ulonglong2* w1bL = &w1qB[0][lane];
    const ulonglong2* w2aL = &w2qA[0][lane];
    const ulonglong2* w2bL = &w2qB[0][lane];
    const float* b1L = b1s + g;

    // b2 quarter, packed (registers)
    ull b2q[4];
#pragma unroll
    for (int d = 0; d < 4; ++d)
        b2q[d] = pack2(b2[8 * s + 2 * d], b2[8 * s + 2 * d + 1]);

    // ---- load initial state: lane's quarter for each of 4 rows ----
    ull y2[RPW][4], acc2[RPW][4], yin2[RPW][4], k2[RPW][4];
#pragma unroll
    for (int r = 0; r < RPW; ++r) {
        const ulonglong2* fp = reinterpret_cast<const ulonglong2*>(
            first_point + (size_t)(rbase + r) * DIM + 8 * s);
        ulonglong2 v0 = fp[0], v1 = fp[1];
        y2[r][0] = v0.x; y2[r][1] = v0.y;
        y2[r][2] = v1.x; y2[r][3] = v1.y;
    }

    // t = 0: lanes g<4 write row g's quarter (coalesced 128B per row)
    if (g < 4) {
        float* dst = out + (size_t)(rbase + g) * (NT * DIM) + 8 * s;
        ulonglong2 v0, v1;
        v0.x = y2[g][0]; v0.y = y2[g][1];
        v1.x = y2[g][2]; v1.y = y2[g][3];
        reinterpret_cast<ulonglong2*>(dst)[0] = v0;
        reinterpret_cast<ulonglong2*>(dst)[1] = v1;
    }

#pragma unroll
    for (int r = 0; r < RPW; ++r)
#pragma unroll
        for (int d = 0; d < 4; ++d) yin2[r][d] = y2[r][d];

    // ---- RK4 time loop: 4 substeps, feval emitted ONCE ----
#pragma unroll 1
    for (int t = 0; t < NT - 1; ++t) {
        const float dt   = tss[t + 1] - tss[t];
        const float dt6f = dt * (1.0f / 6.0f);
        const float dt3f = dt * (1.0f / 3.0f);
        const float dthf = 0.5f * dt;

        // acc starts at y
#pragma unroll
        for (int r = 0; r < RPW; ++r)
#pragma unroll
            for (int d = 0; d < 4; ++d) acc2[r][d] = y2[r][d];

#pragma unroll 1
        for (int sub = 0; sub < 4; ++sub) {
            feval(yin2, k2, w1aL, w1bL, w2aL, w2bL, b1L, b2q, s);

            const float cAf = (sub == 0 || sub == 3) ? dt6f : dt3f;
            const ull cA = pack2(cAf, cAf);

            if (sub < 3) {
                const float cBf = (sub < 2) ? dthf : dt;
                const ull cB = pack2(cBf, cBf);
#pragma unroll
                for (int r = 0; r < RPW; ++r)
#pragma unroll
                    for (int d = 0; d < 4; ++d) {
                        acc2[r][d] = fma2(cA, k2[r][d], acc2[r][d]);
                        yin2[r][d] = fma2(cB, k2[r][d], y2[r][d]);
                    }
            } else {
                // finalize y_{t+1}, reset yin, store
#pragma unroll
                for (int r = 0; r < RPW; ++r)
#pragma unroll
                    for (int d = 0; d < 4; ++d) {
                        y2[r][d] = fma2(cA, k2[r][d], acc2[r][d]);
                        yin2[r][d] = y2[r][d];
                    }
                if (g < 4) {
                    float* dst = out + (size_t)(rbase + g) * (NT * DIM)
                               + (size_t)(t + 1) * DIM + 8 * s;
                    ulonglong2 v0, v1;
                    v0.x = y2[g][0]; v0.y = y2[g][1];
                    v1.x = y2[g][2]; v1.y = y2[g][3];
                    reinterpret_cast<ulonglong2*>(dst)[0] = v0;
                    reinterpret_cast<ulonglong2*>(dst)[1] = v1;
                }
            }
        }
    }
}

extern "C" void kernel_launch(void* const* d_in, const int* in_sizes, int n_in,
                              void* d_out, int out_size) {
    const float* first_point = (const float*)d_in[0];  // [3,1024,32]
    const float* time_steps  = (const float*)d_in[1];  // [256]
    const float* W1          = (const float*)d_in[2];  // [32,128]
    const float* b1          = (const float*)d_in[3];  // [128]
    const float* W2          = (const float*)d_in[4];  // [128,32]
    const float* b2          = (const float*)d_in[5];  // [32]
    float* out = (float*)d_out;                        // [3,1024,256,32]

    rk4_mlp_kernel<<<NBLK, TPB>>>(first_point, time_steps, W1, b1, W2, b2, out);
}

// round 12
// speedup vs baseline: 1.5041x; 1.0928x over previous
#include <cuda_runtime.h>

// RK4 over f(y) = tanh(y@W1+b1)@W2 + b2.  S*B=3072 rows, D=32, H=128, T=256.
//
// R12 = R11 (phase-split feval, single-copy RK4 substep loop; 2768us) +
// W2 register residency for i-planes 0..3 (NC=4): loaded once per thread
// before the time loop, reused for all 1020*4 fevals. Cuts 8 of 64 LDS.128
// per feval-warp (-12.5% smem crossbar) and removes LDS latency from the
// cached half of pass B. Halves are template<BASE> instantiations so the
// cached/uncached choice folds at compile time.
// Layout unchanged: lane=(g=lane&7, s=lane>>3); lane owns j=g+8i and state
// quarter [8s..8s+7]; warp carries 4 rows; weights in smem [i][lane] packs
// (every LDS.128 moves 512B all-unique); slot-dedup'd exp-based tanh.

#define DIM   32
#define HID   128
#define NT    256
#define NROWS 3072
#define TPB   64
#define RPW   4                    // rows per warp
#define RPB   ((TPB/32)*RPW)       // 8 rows per block
#define NBLK  (NROWS/RPB)          // 384
#define NC    4                    // W2 planes cached in registers

typedef unsigned long long ull;

__device__ __forceinline__ ull fma2(ull a, ull b, ull c) {
    ull d;
    asm("fma.rn.f32x2 %0, %1, %2, %3;" : "=l"(d) : "l"(a), "l"(b), "l"(c));
    return d;
}
__device__ __forceinline__ ull add2(ull a, ull b) {
    ull d;
    asm("add.rn.f32x2 %0, %1, %2;" : "=l"(d) : "l"(a), "l"(b));
    return d;
}
__device__ __forceinline__ ull pack2(float lo, float hi) {
    ull d;
    asm("mov.b64 %0, {%1, %2};" : "=l"(d) : "f"(lo), "f"(hi));
    return d;
}
__device__ __forceinline__ void unpack2(ull v, float& lo, float& hi) {
    asm("mov.b64 {%0, %1}, %2;" : "=f"(lo), "=f"(hi) : "l"(v));
}

// accurate fast tanh: 1 - 2/(exp(2x)+1); ~1e-7 abs err, saturates at +/-inf.
__device__ __forceinline__ float tanh_fast(float x) {
    float e = __expf(2.0f * x);
    return 1.0f - __fdividef(2.0f, e + 1.0f);
}

// Half of one f evaluation (8 i-planes starting at BASE) for the warp's 4
// rows. Pass A: dots+butterfly+dedup tanh+rebroadcast, h staged in regs.
// Pass B: scatter; W2 comes from registers for BASE==0 && ii<NC.
template<int BASE>
__device__ __forceinline__ void feval_half(
    const ull in[RPW][4], ull kq[RPW][4],
    const ulonglong2* __restrict__ w1aL, const ulonglong2* __restrict__ w1bL,
    const ulonglong2* __restrict__ w2aL, const ulonglong2* __restrict__ w2bL,
    const ulonglong2 (&vaR)[NC], const ulonglong2 (&vbR)[NC],
    const float* __restrict__ b1L, int s)
{
    const bool sLo = (s & 1) != 0;   // position within s-pair
    const bool sHi = (s & 2) != 0;   // which s-pair

    const ulonglong2* waP = w1aL + BASE * 32;
    const ulonglong2* wbP = w1bL + BASE * 32;
    const ulonglong2* vaP = w2aL + BASE * 32;
    const ulonglong2* vbP = w2bL + BASE * 32;
    const float* b1P = b1L + BASE * 8;

    // ---- pass A ----
    ull h01s[8], h23s[8];
#pragma unroll
    for (int ii = 0; ii < 8; ++ii) {
        const ulonglong2 wa = waP[ii * 32];   // W1[8s+0..3 , j]
        const ulonglong2 wb = wbP[ii * 32];   // W1[8s+4..7 , j]
        const float b1j = b1P[8 * ii];

        float hs[RPW];
#pragma unroll
        for (int r = 0; r < RPW; ++r) {
            ull t0 = fma2(in[r][0], wa.x, 0ull);
            ull t1 = fma2(in[r][2], wb.x, 0ull);
            t0 = fma2(in[r][1], wa.y, t0);
            t1 = fma2(in[r][3], wb.y, t1);
            float lo, hi;
            unpack2(add2(t0, t1), lo, hi);
            hs[r] = lo + hi;
        }

        // butterfly over s (lanes ^8, ^16); 2 rows per packed value
        ull q01 = pack2(hs[0], hs[1]);
        ull q23 = pack2(hs[2], hs[3]);
        q01 = add2(q01, __shfl_xor_sync(0xffffffffu, q01, 8));
        q23 = add2(q23, __shfl_xor_sync(0xffffffffu, q23, 8));
        q01 = add2(q01, __shfl_xor_sync(0xffffffffu, q01, 16));
        q23 = add2(q23, __shfl_xor_sync(0xffffffffu, q23, 16));
        float f0, f1, f2, f3;
        unpack2(q01, f0, f1);
        unpack2(q23, f2, f3);

        // slot s evaluates ONLY row s's tanh (dedup)
        const float fA = sLo ? f1 : f0;
        const float fB = sLo ? f3 : f2;
        const float fs = sHi ? fB : fA;
        const float h  = tanh_fast(fs + b1j);

        // re-broadcast the 4 h's: ^8 (scalar) then ^16 (packed)
        const float ho = __shfl_xor_sync(0xffffffffu, h, 8);
        const float hl = sLo ? ho : h;
        const float hu = sLo ? h : ho;
        const ull hp = pack2(hl, hu);
        const ull hq = __shfl_xor_sync(0xffffffffu, hp, 16);
        h01s[ii] = sHi ? hq : hp;        // (h0, h1)
        h23s[ii] = sHi ? hp : hq;        // (h2, h3)
    }

    // ---- pass B: scatter (W2 from regs for cached planes) ----
#pragma unroll
    for (int ii = 0; ii < 8; ++ii) {
        const bool useR = (BASE == 0) && (ii < NC);
        const ulonglong2 va = useR ? vaR[ii < NC ? ii : 0] : vaP[ii * 32];
        const ulonglong2 vb = useR ? vbR[ii < NC ? ii : 0] : vbP[ii * 32];
        float h0, h1, h2, h3;
        unpack2(h01s[ii], h0, h1);
        unpack2(h23s[ii], h2, h3);
        ull hhr[RPW];
        hhr[0] = pack2(h0, h0);
        hhr[1] = pack2(h1, h1);
        hhr[2] = pack2(h2, h2);
        hhr[3] = pack2(h3, h3);
#pragma unroll
        for (int r = 0; r < RPW; ++r) {
            kq[r][0] = fma2(hhr[r], va.x, kq[r][0]);
            kq[r][1] = fma2(hhr[r], va.y, kq[r][1]);
            kq[r][2] = fma2(hhr[r], vb.x, kq[r][2]);
            kq[r][3] = fma2(hhr[r], vb.y, kq[r][3]);
        }
    }
}

// One f evaluation for the warp's 4 rows.
__device__ __forceinline__ void feval(
    const ull in[RPW][4], ull kq[RPW][4],
    const ulonglong2* __restrict__ w1aL, const ulonglong2* __restrict__ w1bL,
    const ulonglong2* __restrict__ w2aL, const ulonglong2* __restrict__ w2bL,
    const ulonglong2 (&vaR)[NC], const ulonglong2 (&vbR)[NC],
    const float* __restrict__ b1L, const ull b2q[4], int s)
{
#pragma unroll
    for (int r = 0; r < RPW; ++r)
#pragma unroll
        for (int d = 0; d < 4; ++d) kq[r][d] = 0ull;

    feval_half<0>(in, kq, w1aL, w1bL, w2aL, w2bL, vaR, vbR, b1L, s);
    feval_half<8>(in, kq, w1aL, w1bL, w2aL, w2bL, vaR, vbR, b1L, s);

    // reduce partial k over the 8 g-lanes (lanes ^1, ^2, ^4), then + b2
#pragma unroll
    for (int m = 1; m < 8; m <<= 1) {
#pragma unroll
        for (int r = 0; r < RPW; ++r)
#pragma unroll
            for (int d = 0; d < 4; ++d)
                kq[r][d] = add2(kq[r][d],
                                __shfl_xor_sync(0xffffffffu, kq[r][d], m));
    }
#pragma unroll
    for (int r = 0; r < RPW; ++r)
#pragma unroll
        for (int d = 0; d < 4; ++d) kq[r][d] = add2(kq[r][d], b2q[d]);
}

__global__ __launch_bounds__(TPB)
void rk4_mlp_kernel(
    const float* __restrict__ first_point,   // [3072, 32]
    const float* __restrict__ time_steps,    // [256]
    const float* __restrict__ W1,            // [32, 128]
    const float* __restrict__ b1,            // [128]
    const float* __restrict__ W2,            // [128, 32]
    const float* __restrict__ b2,            // [32]
    float* __restrict__ out)                 // [3072, 256, 32]
{
    // weight packs: [i][lane]; every warp LDS.128 is 512B all-unique
    __shared__ ulonglong2 w1qA[16][32];  // float4 = W1[8s+0..3 , g+8i]
    __shared__ ulonglong2 w1qB[16][32];  // float4 = W1[8s+4..7 , g+8i]
    __shared__ ulonglong2 w2qA[16][32];  // float4 = W2[g+8i][8s+0..3]
    __shared__ ulonglong2 w2qB[16][32];  // float4 = W2[g+8i][8s+4..7]
    __shared__ float b1s[HID];
    __shared__ float tss[NT];

    const int tid = threadIdx.x;

    // ---- stage weights (one-time; scalar writes) ----
    {
        float* a1 = (float*)w1qA; float* a2 = (float*)w1qB;
        float* a3 = (float*)w2qA; float* a4 = (float*)w2qB;
        for (int idx = tid; idx < 16 * 32 * 4; idx += TPB) {
            const int i  = idx >> 7;          // plane
            const int ln = (idx >> 2) & 31;   // lane
            const int f  = idx & 3;           // float within float4
            const int ss = ln >> 3, gg = ln & 7;
            const int j  = gg + 8 * i;
            a1[idx] = W1[(8 * ss + f)     * HID + j];
            a2[idx] = W1[(8 * ss + 4 + f) * HID + j];
            a3[idx] = W2[j * DIM + 8 * ss + f];
            a4[idx] = W2[j * DIM + 8 * ss + 4 + f];
        }
        for (int idx = tid; idx < HID; idx += TPB) b1s[idx] = b1[idx];
        for (int idx = tid; idx < NT;  idx += TPB) tss[idx] = time_steps[idx];
    }
    __syncthreads();

    const int lane = tid & 31;
    const int warp = tid >> 5;
    const int g = lane & 7;
    const int s = lane >> 3;
    const int rbase = blockIdx.x * RPB + warp * RPW;

    const ulonglong2* w1aL = &w1qA[0][lane];
    const ulonglong2* w1bL = &w1qB[0][lane];
    const ulonglong2* w2aL = &w2qA[0][lane];
    const ulonglong2* w2bL = &w2qB[0][lane];
    const float* b1L = b1s + g;

    // W2 planes 0..NC-1 resident in registers (reused 4080x)
    ulonglong2 vaR[NC], vbR[NC];
#pragma unroll
    for (int p = 0; p < NC; ++p) {
        vaR[p] = w2aL[p * 32];
        vbR[p] = w2bL[p * 32];
    }

    // b2 quarter, packed (registers)
    ull b2q[4];
#pragma unroll
    for (int d = 0; d < 4; ++d)
        b2q[d] = pack2(b2[8 * s + 2 * d], b2[8 * s + 2 * d + 1]);

    // ---- load initial state: lane's quarter for each of 4 rows ----
    ull y2[RPW][4], acc2[RPW][4], yin2[RPW][4], k2[RPW][4];
#pragma unroll
    for (int r = 0; r < RPW; ++r) {
        const ulonglong2* fp = reinterpret_cast<const ulonglong2*>(
            first_point + (size_t)(rbase + r) * DIM + 8 * s);
        ulonglong2 v0 = fp[0], v1 = fp[1];
        y2[r][0] = v0.x; y2[r][1] = v0.y;
        y2[r][2] = v1.x; y2[r][3] = v1.y;
    }

    // t = 0: lanes g<4 write row g's quarter (coalesced 128B per row)
    if (g < 4) {
        float* dst = out + (size_t)(rbase + g) * (NT * DIM) + 8 * s;
        ulonglong2 v0, v1;
        v0.x = y2[g][0]; v0.y = y2[g][1];
        v1.x = y2[g][2]; v1.y = y2[g][3];
        reinterpret_cast<ulonglong2*>(dst)[0] = v0;
        reinterpret_cast<ulonglong2*>(dst)[1] = v1;
    }

#pragma unroll
    for (int r = 0; r < RPW; ++r)
#pragma unroll
        for (int d = 0; d < 4; ++d) yin2[r][d] = y2[r][d];

    // ---- RK4 time loop: 4 substeps, feval emitted ONCE ----
#pragma unroll 1
    for (int t = 0; t < NT - 1; ++t) {
        const float dt   = tss[t + 1] - tss[t];
        const float dt6f = dt * (1.0f / 6.0f);
        const float dt3f = dt * (1.0f / 3.0f);
        const float dthf = 0.5f * dt;

        // acc starts at y
#pragma unroll
        for (int r = 0; r < RPW; ++r)
#pragma unroll
            for (int d = 0; d < 4; ++d) acc2[r][d] = y2[r][d];

#pragma unroll 1
        for (int sub = 0; sub < 4; ++sub) {
            feval(yin2, k2, w1aL, w1bL, w2aL, w2bL, vaR, vbR, b1L, b2q, s);

            const float cAf = (sub == 0 || sub == 3) ? dt6f : dt3f;
            const ull cA = pack2(cAf, cAf);

            if (sub < 3) {
                const float cBf = (sub < 2) ? dthf : dt;
                const ull cB = pack2(cBf, cBf);
#pragma unroll
                for (int r = 0; r < RPW; ++r)
#pragma unroll
                    for (int d = 0; d < 4; ++d) {
                        acc2[r][d] = fma2(cA, k2[r][d], acc2[r][d]);
                        yin2[r][d] = fma2(cB, k2[r][d], y2[r][d]);
                    }
            } else {
                // finalize y_{t+1}, reset yin, store
#pragma unroll
                for (int r = 0; r < RPW; ++r)
#pragma unroll
                    for (int d = 0; d < 4; ++d) {
                        y2[r][d] = fma2(cA, k2[r][d], acc2[r][d]);
                        yin2[r][d] = y2[r][d];
                    }
                if (g < 4) {
                    float* dst = out + (size_t)(rbase + g) * (NT * DIM)
                               + (size_t)(t + 1) * DIM + 8 * s;
                    ulonglong2 v0, v1;
                    v0.x = y2[g][0]; v0.y = y2[g][1];
                    v1.x = y2[g][2]; v1.y = y2[g][3];
                    reinterpret_cast<ulonglong2*>(dst)[0] = v0;
                    reinterpret_cast<ulonglong2*>(dst)[1] = v1;
                }
            }
        }
    }
}

extern "C" void kernel_launch(void* const* d_in, const int* in_sizes, int n_in,
                              void* d_out, int out_size) {
    const float* first_point = (const float*)d_in[0];  // [3,1024,32]
    const float* time_steps  = (const float*)d_in[1];  // [256]
    const float* W1          = (const float*)d_in[2];  // [32,128]
    const float* b1          = (const float*)d_in[3];  // [128]
    const float* W2          = (const float*)d_in[4];  // [128,32]
    const float* b2          = (const float*)d_in[5];  // [32]
    float* out = (float*)d_out;                        // [3,1024,256,32]

    rk4_mlp_kernel<<<NBLK, TPB>>>(first_point, time_steps, W1, b1, W2, b2, out);
}

// round 13
// speedup vs baseline: 1.5044x; 1.0002x over previous
#include <cuda_runtime.h>

// RK4 over f(y) = tanh(y@W1+b1)@W2 + b2.  S*B=3072 rows, D=32, H=128, T=256.
//
// R13 = R12 (2533us) with:
//  (a) 3-shfl dot reduction (was 4): after the ^8 round, lane s only needs
//      row s's full sum -> single ^16 exchange of the partial the partner
//      pair needs, instead of all-reducing both packed values.
//  (b) pass A stages pre-tanh scalars fs[8] (8 regs) instead of post-tanh
//      packed h (32 regs); tanh + rebroadcast start pass B (still 8
//      independent chains). Frees ~24 regs.
//  (c) freed regs spent on NC=6 W2 planes in registers (was 4):
//      LDS.128/feval 56 -> 52, and regs drop off the 255 cap.
// Layout unchanged: lane=(g=lane&7, s=lane>>3); lane owns j=g+8i and state
// quarter [8s..8s+7]; warp carries 4 rows, autonomous (no block barriers).

#define DIM   32
#define HID   128
#define NT    256
#define NROWS 3072
#define TPB   64
#define RPW   4                    // rows per warp
#define RPB   ((TPB/32)*RPW)       // 8 rows per block
#define NBLK  (NROWS/RPB)          // 384
#define NC    6                    // W2 planes cached in registers

typedef unsigned long long ull;

__device__ __forceinline__ ull fma2(ull a, ull b, ull c) {
    ull d;
    asm("fma.rn.f32x2 %0, %1, %2, %3;" : "=l"(d) : "l"(a), "l"(b), "l"(c));
    return d;
}
__device__ __forceinline__ ull add2(ull a, ull b) {
    ull d;
    asm("add.rn.f32x2 %0, %1, %2;" : "=l"(d) : "l"(a), "l"(b));
    return d;
}
__device__ __forceinline__ ull pack2(float lo, float hi) {
    ull d;
    asm("mov.b64 %0, {%1, %2};" : "=l"(d) : "f"(lo), "f"(hi));
    return d;
}
__device__ __forceinline__ void unpack2(ull v, float& lo, float& hi) {
    asm("mov.b64 {%0, %1}, %2;" : "=f"(lo), "=f"(hi) : "l"(v));
}

// accurate fast tanh: 1 - 2/(exp(2x)+1); ~1e-7 abs err, saturates at +/-inf.
__device__ __forceinline__ float tanh_fast(float x) {
    float e = __expf(2.0f * x);
    return 1.0f - __fdividef(2.0f, e + 1.0f);
}

// Half of one f evaluation (8 i-planes starting at BASE) for the warp's 4
// rows. Pass A: dots + 3-shfl row-targeted reduce -> stage fs scalars.
// Pass B: tanh + 2-shfl rebroadcast + scatter (W2 from regs for cached
// planes when BASE==0).
template<int BASE>
__device__ __forceinline__ void feval_half(
    const ull in[RPW][4], ull kq[RPW][4],
    const ulonglong2* __restrict__ w1aL, const ulonglong2* __restrict__ w1bL,
    const ulonglong2* __restrict__ w2aL, const ulonglong2* __restrict__ w2bL,
    const ulonglong2 (&vaR)[NC], const ulonglong2 (&vbR)[NC],
    const float* __restrict__ b1L, int s)
{
    const bool sLo = (s & 1) != 0;   // position within s-pair
    const bool sHi = (s & 2) != 0;   // which s-pair (-> which row-pair I own)

    const ulonglong2* waP = w1aL + BASE * 32;
    const ulonglong2* wbP = w1bL + BASE * 32;
    const ulonglong2* vaP = w2aL + BASE * 32;
    const ulonglong2* vbP = w2bL + BASE * 32;
    const float* b1P = b1L + BASE * 8;

    // ---- pass A: dots + reduce; stage pre-tanh scalars (8 regs) ----
    float fsst[8];
#pragma unroll
    for (int ii = 0; ii < 8; ++ii) {
        const ulonglong2 wa = waP[ii * 32];   // W1[8s+0..3 , j]
        const ulonglong2 wb = wbP[ii * 32];   // W1[8s+4..7 , j]

        float hs[RPW];
#pragma unroll
        for (int r = 0; r < RPW; ++r) {
            ull t0 = fma2(in[r][0], wa.x, 0ull);
            ull t1 = fma2(in[r][2], wb.x, 0ull);
            t0 = fma2(in[r][1], wa.y, t0);
            t1 = fma2(in[r][3], wb.y, t1);
            float lo, hi;
            unpack2(add2(t0, t1), lo, hi);
            hs[r] = lo + hi;
        }

        // stage 1: reduce over s-pair (^8); 2 rows per packed value
        ull q01 = pack2(hs[0], hs[1]);
        ull q23 = pack2(hs[2], hs[3]);
        q01 = add2(q01, __shfl_xor_sync(0xffffffffu, q01, 8));
        q23 = add2(q23, __shfl_xor_sync(0xffffffffu, q23, 8));
        // stage 2: single ^16 exchange — send what the partner pair needs,
        // receive what I need (my row-pair = rows {2*sHi, 2*sHi+1})
        const ull send = sHi ? q01 : q23;
        const ull recv = __shfl_xor_sync(0xffffffffu, send, 16);
        const ull mine = sHi ? q23 : q01;
        float flo, fhi;
        unpack2(add2(mine, recv), flo, fhi);
        fsst[ii] = (sLo ? fhi : flo) + b1P[8 * ii];   // my row's pre-tanh
    }

    // ---- pass B: tanh + rebroadcast + scatter ----
#pragma unroll
    for (int ii = 0; ii < 8; ++ii) {
        const float h = tanh_fast(fsst[ii]);          // row s's h only
        // rebroadcast 4 h's: ^8 (scalar) then ^16 (packed)
        const float ho = __shfl_xor_sync(0xffffffffu, h, 8);
        const float hl = sLo ? ho : h;
        const float hu = sLo ? h : ho;
        const ull hp = pack2(hl, hu);
        const ull hq = __shfl_xor_sync(0xffffffffu, hp, 16);
        const ull h01 = sHi ? hq : hp;   // (h0, h1)
        const ull h23 = sHi ? hp : hq;   // (h2, h3)
        float h0, h1, h2, h3;
        unpack2(h01, h0, h1);
        unpack2(h23, h2, h3);
        ull hhr[RPW];
        hhr[0] = pack2(h0, h0);
        hhr[1] = pack2(h1, h1);
        hhr[2] = pack2(h2, h2);
        hhr[3] = pack2(h3, h3);

        const bool useR = (BASE == 0) && (ii < NC);
        const ulonglong2 va = useR ? vaR[ii < NC ? ii : 0] : vaP[ii * 32];
        const ulonglong2 vb = useR ? vbR[ii < NC ? ii : 0] : vbP[ii * 32];
#pragma unroll
        for (int r = 0; r < RPW; ++r) {
            kq[r][0] = fma2(hhr[r], va.x, kq[r][0]);
            kq[r][1] = fma2(hhr[r], va.y, kq[r][1]);
            kq[r][2] = fma2(hhr[r], vb.x, kq[r][2]);
            kq[r][3] = fma2(hhr[r], vb.y, kq[r][3]);
        }
    }
}

// One f evaluation for the warp's 4 rows.
__device__ __forceinline__ void feval(
    const ull in[RPW][4], ull kq[RPW][4],
    const ulonglong2* __restrict__ w1aL, const ulonglong2* __restrict__ w1bL,
    const ulonglong2* __restrict__ w2aL, const ulonglong2* __restrict__ w2bL,
    const ulonglong2 (&vaR)[NC], const ulonglong2 (&vbR)[NC],
    const float* __restrict__ b1L, const ull b2q[4], int s)
{
#pragma unroll
    for (int r = 0; r < RPW; ++r)
#pragma unroll
        for (int d = 0; d < 4; ++d) kq[r][d] = 0ull;

    feval_half<0>(in, kq, w1aL, w1bL, w2aL, w2bL, vaR, vbR, b1L, s);
    feval_half<8>(in, kq, w1aL, w1bL, w2aL, w2bL, vaR, vbR, b1L, s);

    // reduce partial k over the 8 g-lanes (lanes ^1, ^2, ^4), then + b2
#pragma unroll
    for (int m = 1; m < 8; m <<= 1) {
#pragma unroll
        for (int r = 0; r < RPW; ++r)
#pragma unroll
            for (int d = 0; d < 4; ++d)
                kq[r][d] = add2(kq[r][d],
                                __shfl_xor_sync(0xffffffffu, kq[r][d], m));
    }
#pragma unroll
    for (int r = 0; r < RPW; ++r)
#pragma unroll
        for (int d = 0; d < 4; ++d) kq[r][d] = add2(kq[r][d], b2q[d]);
}

__global__ __launch_bounds__(TPB)
void rk4_mlp_kernel(
    const float* __restrict__ first_point,   // [3072, 32]
    const float* __restrict__ time_steps,    // [256]
    const float* __restrict__ W1,            // [32, 128]
    const float* __restrict__ b1,            // [128]
    const float* __restrict__ W2,            // [128, 32]
    const float* __restrict__ b2,            // [32]
    float* __restrict__ out)                 // [3072, 256, 32]
{
    // weight packs: [i][lane]; every warp LDS.128 is 512B all-unique
    __shared__ ulonglong2 w1qA[16][32];  // float4 = W1[8s+0..3 , g+8i]
    __shared__ ulonglong2 w1qB[16][32];  // float4 = W1[8s+4..7 , g+8i]
    __shared__ ulonglong2 w2qA[16][32];  // float4 = W2[g+8i][8s+0..3]
    __shared__ ulonglong2 w2qB[16][32];  // float4 = W2[g+8i][8s+4..7]
    __shared__ float b1s[HID];
    __shared__ float tss[NT];

    const int tid = threadIdx.x;

    // ---- stage weights (one-time; scalar writes) ----
    {
        float* a1 = (float*)w1qA; float* a2 = (float*)w1qB;
        float* a3 = (float*)w2qA; float* a4 = (float*)w2qB;
        for (int idx = tid; idx < 16 * 32 * 4; idx += TPB) {
            const int i  = idx >> 7;          // plane
            const int ln = (idx >> 2) & 31;   // lane
            const int f  = idx & 3;           // float within float4
            const int ss = ln >> 3, gg = ln & 7;
            const int j  = gg + 8 * i;
            a1[idx] = W1[(8 * ss + f)     * HID + j];
            a2[idx] = W1[(8 * ss + 4 + f) * HID + j];
            a3[idx] = W2[j * DIM + 8 * ss + f];
            a4[idx] = W2[j * DIM + 8 * ss + 4 + f];
        }
        for (int idx = tid; idx < HID; idx += TPB) b1s[idx] = b1[idx];
        for (int idx = tid; idx < NT;  idx += TPB) tss[idx] = time_steps[idx];
    }
    __syncthreads();

    const int lane = tid & 31;
    const int warp = tid >> 5;
    const int g = lane & 7;
    const int s = lane >> 3;
    const int rbase = blockIdx.x * RPB + warp * RPW;

    const ulonglong2* w1aL = &w1qA[0][lane];
    const ulonglong2* w1bL = &w1qB[0][lane];
    const ulonglong2* w2aL = &w2qA[0][lane];
    const ulonglong2* w2bL = &w2qB[0][lane];
    const float* b1L = b1s + g;

    // W2 planes 0..NC-1 resident in registers (reused 4080x)
    ulonglong2 vaR[NC], vbR[NC];
#pragma unroll
    for (int p = 0; p < NC; ++p) {
        vaR[p] = w2aL[p * 32];
        vbR[p] = w2bL[p * 32];
    }

    // b2 quarter, packed (registers)
    ull b2q[4];
#pragma unroll
    for (int d = 0; d < 4; ++d)
        b2q[d] = pack2(b2[8 * s + 2 * d], b2[8 * s + 2 * d + 1]);

    // ---- load initial state: lane's quarter for each of 4 rows ----
    ull y2[RPW][4], acc2[RPW][4], yin2[RPW][4], k2[RPW][4];
#pragma unroll
    for (int r = 0; r < RPW; ++r) {
        const ulonglong2* fp = reinterpret_cast<const ulonglong2*>(
            first_point + (size_t)(rbase + r) * DIM + 8 * s);
        ulonglong2 v0 = fp[0], v1 = fp[1];
        y2[r][0] = v0.x; y2[r][1] = v0.y;
        y2[r][2] = v1.x; y2[r][3] = v1.y;
    }

    // t = 0: lanes g<4 write row g's quarter (coalesced 128B per row)
    if (g < 4) {
        float* dst = out + (size_t)(rbase + g) * (NT * DIM) + 8 * s;
        ulonglong2 v0, v1;
        v0.x = y2[g][0]; v0.y = y2[g][1];
        v1.x = y2[g][2]; v1.y = y2[g][3];
        reinterpret_cast<ulonglong2*>(dst)[0] = v0;
        reinterpret_cast<ulonglong2*>(dst)[1] = v1;
    }

#pragma unroll
    for (int r = 0; r < RPW; ++r)
#pragma unroll
        for (int d = 0; d < 4; ++d) yin2[r][d] = y2[r][d];

    // ---- RK4 time loop: 4 substeps, feval emitted ONCE ----
#pragma unroll 1
    for (int t = 0; t < NT - 1; ++t) {
        const float dt   = tss[t + 1] - tss[t];
        const float dt6f = dt * (1.0f / 6.0f);
        const float dt3f = dt * (1.0f / 3.0f);
        const float dthf = 0.5f * dt;

        // acc starts at y
#pragma unroll
        for (int r = 0; r < RPW; ++r)
#pragma unroll
            for (int d = 0; d < 4; ++d) acc2[r][d] = y2[r][d];

#pragma unroll 1
        for (int sub = 0; sub < 4; ++sub) {
            feval(yin2, k2, w1aL, w1bL, w2aL, w2bL, vaR, vbR, b1L, b2q, s);

            const float cAf = (sub == 0 || sub == 3) ? dt6f : dt3f;
            const ull cA = pack2(cAf, cAf);

            if (sub < 3) {
                const float cBf = (sub < 2) ? dthf : dt;
                const ull cB = pack2(cBf, cBf);
#pragma unroll
                for (int r = 0; r < RPW; ++r)
#pragma unroll
                    for (int d = 0; d < 4; ++d) {
                        acc2[r][d] = fma2(cA, k2[r][d], acc2[r][d]);
                        yin2[r][d] = fma2(cB, k2[r][d], y2[r][d]);
                    }
            } else {
                // finalize y_{t+1}, reset yin, store
#pragma unroll
                for (int r = 0; r < RPW; ++r)
#pragma unroll
                    for (int d = 0; d < 4; ++d) {
                        y2[r][d] = fma2(cA, k2[r][d], acc2[r][d]);
                        yin2[r][d] = y2[r][d];
                    }
                if (g < 4) {
                    float* dst = out + (size_t)(rbase + g) * (NT * DIM)
                               + (size_t)(t + 1) * DIM + 8 * s;
                    ulonglong2 v0, v1;
                    v0.x = y2[g][0]; v0.y = y2[g][1];
                    v1.x = y2[g][2]; v1.y = y2[g][3];
                    reinterpret_cast<ulonglong2*>(dst)[0] = v0;
                    reinterpret_cast<ulonglong2*>(dst)[1] = v1;
                }
            }
        }
    }
}

extern "C" void kernel_launch(void* const* d_in, const int* in_sizes, int n_in,
                              void* d_out, int out_size) {
    const float* first_point = (const float*)d_in[0];  // [3,1024,32]
    const float* time_steps  = (const float*)d_in[1];  // [256]
    const float* W1          = (const float*)d_in[2];  // [32,128]
    const float* b1          = (const float*)d_in[3];  // [128]
    const float* W2          = (const float*)d_in[4];  // [128,32]
    const float* b2          = (const float*)d_in[5];  // [32]
    float* out = (float*)d_out;                        // [3,1024,256,32]

    rk4_mlp_kernel<<<NBLK, TPB>>>(first_point, time_steps, W1, b1, W2, b2, out);
}